// round 4
// baseline (speedup 1.0000x reference)
#include <cuda_runtime.h>
#include <cuda_bf16.h>

#define N_NODES 50000
#define E_MAX   800000
#define D_IN 128
#define D_H 96
#define D_OUT 32

// ---------------------------------------------------------------------------
// Scratch (__device__ globals; allocation-free rule)
// ---------------------------------------------------------------------------
__device__ float g_h1[N_NODES * D_H];       // x @ W1
__device__ float g_h2[N_NODES * D_OUT];     // relu(A@h1) @ W2
__device__ int   g_deg[N_NODES];            // degree counts / fill cursor
__device__ int   g_start[N_NODES + 1];      // CSR row starts (by dst)
__device__ int2  g_pair[E_MAX];             // per-edge {src, val_bits}, CSR order

// ---------------------------------------------------------------------------
// GEMM1: h1 = x @ W1   [50000,128]@[128,96]. Register tile 4 rows x 1 col.
// ---------------------------------------------------------------------------
#define G1_PAD  132
#define G1_ROWS 16
#define G1_ITER 4
#define G1_SMEM ((D_H * G1_PAD + G1_ROWS * G1_PAD) * sizeof(float))

__global__ void gemm1_kernel(const float* __restrict__ x,
                             const float* __restrict__ W1) {
    extern __shared__ float smem[];
    float* sWt = smem;                    // [96][132]  sWt[c][k] = W1[k][c]
    float* sx  = smem + D_H * G1_PAD;     // [16][132]

    const int tx = threadIdx.x, ty = threadIdx.y;
    const int t  = ty * 96 + tx;

    for (int i = t; i < D_IN * D_H; i += 384) {
        int k = i / D_H, c = i % D_H;
        sWt[c * G1_PAD + k] = W1[i];
    }
    __syncthreads();

    for (int it = 0; it < G1_ITER; it++) {
        int rowBase = (blockIdx.x * G1_ITER + it) * G1_ROWS;

        for (int i = t; i < G1_ROWS * D_IN; i += 384) {
            int r = i >> 7, k = i & 127;
            int row = rowBase + r;
            sx[r * G1_PAD + k] = (row < N_NODES) ? x[row * D_IN + k] : 0.f;
        }
        __syncthreads();

        float acc0 = 0.f, acc1 = 0.f, acc2 = 0.f, acc3 = 0.f;
        const float4* wrow = (const float4*)(sWt + tx * G1_PAD);
        const float4* xr0  = (const float4*)(sx + (ty * 4 + 0) * G1_PAD);
        const float4* xr1  = (const float4*)(sx + (ty * 4 + 1) * G1_PAD);
        const float4* xr2  = (const float4*)(sx + (ty * 4 + 2) * G1_PAD);
        const float4* xr3  = (const float4*)(sx + (ty * 4 + 3) * G1_PAD);

#pragma unroll
        for (int k4 = 0; k4 < D_IN / 4; k4++) {
            float4 w = wrow[k4];
            float4 v;
            v = xr0[k4]; acc0 = fmaf(v.x,w.x,fmaf(v.y,w.y,fmaf(v.z,w.z,fmaf(v.w,w.w,acc0))));
            v = xr1[k4]; acc1 = fmaf(v.x,w.x,fmaf(v.y,w.y,fmaf(v.z,w.z,fmaf(v.w,w.w,acc1))));
            v = xr2[k4]; acc2 = fmaf(v.x,w.x,fmaf(v.y,w.y,fmaf(v.z,w.z,fmaf(v.w,w.w,acc2))));
            v = xr3[k4]; acc3 = fmaf(v.x,w.x,fmaf(v.y,w.y,fmaf(v.z,w.z,fmaf(v.w,w.w,acc3))));
        }

        int r0 = rowBase + ty * 4;
        if (r0 + 0 < N_NODES) g_h1[(r0 + 0) * D_H + tx] = acc0;
        if (r0 + 1 < N_NODES) g_h1[(r0 + 1) * D_H + tx] = acc1;
        if (r0 + 2 < N_NODES) g_h1[(r0 + 2) * D_H + tx] = acc2;
        if (r0 + 3 < N_NODES) g_h1[(r0 + 3) * D_H + tx] = acc3;
        __syncthreads();
    }
}

// ---------------------------------------------------------------------------
// CSR build: zero degrees -> count -> scan (1 block) -> fill
// ---------------------------------------------------------------------------
__global__ void zero_deg_kernel() {
    int i = blockIdx.x * blockDim.x + threadIdx.x;
    if (i < N_NODES) g_deg[i] = 0;
}

__global__ void count_kernel(const int* __restrict__ dst, int n_edges) {
    int e = blockIdx.x * blockDim.x + threadIdx.x;
    if (e < n_edges) atomicAdd(&g_deg[dst[e]], 1);
}

// Single-block exclusive scan over g_deg -> g_start; resets g_deg to 0 (cursor).
__global__ void scan_kernel() {
    __shared__ int sp[1024];
    const int CH = (N_NODES + 1023) / 1024;   // 49
    int t = threadIdx.x;
    int base = t * CH;

    int sum = 0;
    for (int i = 0; i < CH; i++) {
        int idx = base + i;
        if (idx < N_NODES) sum += g_deg[idx];
    }
    sp[t] = sum;
    __syncthreads();

    // Hillis-Steele inclusive scan
    for (int off = 1; off < 1024; off <<= 1) {
        int v = (t >= off) ? sp[t - off] : 0;
        __syncthreads();
        if (t >= off) sp[t] += v;
        __syncthreads();
    }

    int run = (t == 0) ? 0 : sp[t - 1];
    for (int i = 0; i < CH; i++) {
        int idx = base + i;
        if (idx < N_NODES) {
            g_start[idx] = run;
            run += g_deg[idx];
            g_deg[idx] = 0;          // reset for use as fill cursor
        }
    }
    if (t == 1023) g_start[N_NODES] = run;
}

__global__ void fill_kernel(const int* __restrict__ src,
                            const int* __restrict__ dst,
                            const float* __restrict__ val,
                            int n_edges) {
    int e = blockIdx.x * blockDim.x + threadIdx.x;
    if (e >= n_edges) return;
    int d = dst[e];
    int pos = g_start[d] + atomicAdd(&g_deg[d], 1);
    g_pair[pos] = make_int2(src[e], __float_as_int(val[e]));
}

// ---------------------------------------------------------------------------
// Fused layer 1 aggregation + relu + GEMM2:
//   h2[n] = relu( sum_{e in CSR[n]} val_e * h1[src_e] ) @ W2
// One warp per node. Lanes 0..23 gather/accumulate float4 chunks of the
// 96-wide row; row staged in per-warp smem; then lane c computes output col c
// against W2 (natural [k][c] layout -> conflict-free LDS).
// ---------------------------------------------------------------------------
#define FW_WARPS 8
#define SROW_PAD 100

__global__ void fused_agg_gemm2_kernel(const float* __restrict__ W2) {
    __shared__ float sW2[D_H * D_OUT];              // [96][32], 12 KB
    __shared__ float srow[FW_WARPS][SROW_PAD];      // per-warp agg row

    int t = threadIdx.x;
    for (int i = t; i < D_H * D_OUT; i += blockDim.x) sW2[i] = W2[i];
    __syncthreads();

    int w    = t >> 5;
    int lane = t & 31;
    int n    = blockIdx.x * FW_WARPS + w;
    if (n >= N_NODES) return;

    int pBeg = g_start[n];
    int pEnd = g_start[n + 1];

    float ax = 0.f, ay = 0.f, az = 0.f, aw = 0.f;
    if (lane < 24) {
        for (int p = pBeg; p < pEnd; p++) {
            int2 pr = g_pair[p];                      // broadcast load
            float v = __int_as_float(pr.y);
            float4 h = *reinterpret_cast<const float4*>(
                g_h1 + (long)pr.x * D_H + lane * 4);
            ax = fmaf(v, h.x, ax);
            ay = fmaf(v, h.y, ay);
            az = fmaf(v, h.z, az);
            aw = fmaf(v, h.w, aw);
        }
        float4 r = make_float4(fmaxf(ax, 0.f), fmaxf(ay, 0.f),
                               fmaxf(az, 0.f), fmaxf(aw, 0.f));
        *reinterpret_cast<float4*>(&srow[w][lane * 4]) = r;
    }
    __syncwarp();

    // lane = output column; srow broadcast, sW2 conflict-free
    float acc = 0.f;
    const float4* sr4 = reinterpret_cast<const float4*>(&srow[w][0]);
#pragma unroll
    for (int k4 = 0; k4 < D_H / 4; k4++) {
        float4 s = sr4[k4];
        int k = k4 * 4;
        acc = fmaf(s.x, sW2[(k + 0) * D_OUT + lane], acc);
        acc = fmaf(s.y, sW2[(k + 1) * D_OUT + lane], acc);
        acc = fmaf(s.z, sW2[(k + 2) * D_OUT + lane], acc);
        acc = fmaf(s.w, sW2[(k + 3) * D_OUT + lane], acc);
    }
    g_h2[(long)n * D_OUT + lane] = acc;
}

// ---------------------------------------------------------------------------
// Layer 2 aggregation (gather): out[n] = sum val_e * h2[src_e]. One warp/node,
// lane = column (coalesced 128B gathers). Writes every row (covers poison).
// ---------------------------------------------------------------------------
__global__ void spmm2_gather_kernel(float* __restrict__ out) {
    int t    = threadIdx.x;
    int w    = t >> 5;
    int lane = t & 31;
    int n    = blockIdx.x * FW_WARPS + w;
    if (n >= N_NODES) return;

    int pBeg = g_start[n];
    int pEnd = g_start[n + 1];

    float acc = 0.f;
    for (int p = pBeg; p < pEnd; p++) {
        int2 pr = g_pair[p];
        float v = __int_as_float(pr.y);
        acc = fmaf(v, g_h2[(long)pr.x * D_OUT + lane], acc);
    }
    out[(long)n * D_OUT + lane] = acc;
}

// ---------------------------------------------------------------------------
// Launch: zero_deg -> count -> gemm1 -> scan -> fill -> fused -> spmm2
// ---------------------------------------------------------------------------
extern "C" void kernel_launch(void* const* d_in, const int* in_sizes, int n_in,
                              void* d_out, int out_size) {
    const float* x        = (const float*)d_in[0];
    const int*   edge_src = (const int*)  d_in[1];
    const int*   edge_dst = (const int*)  d_in[2];
    const float* edge_val = (const float*)d_in[3];
    const float* W1       = (const float*)d_in[4];
    const float* W2       = (const float*)d_in[5];
    float*       out      = (float*)d_out;

    int E = in_sizes[1];

    cudaFuncSetAttribute(gemm1_kernel,
                         cudaFuncAttributeMaxDynamicSharedMemorySize,
                         (int)G1_SMEM);

    zero_deg_kernel<<<(N_NODES + 255) / 256, 256>>>();
    count_kernel<<<(E + 255) / 256, 256>>>(edge_dst, E);

    dim3 g1_block(96, 4);
    int  g1_grid = (N_NODES + G1_ROWS * G1_ITER - 1) / (G1_ROWS * G1_ITER);
    gemm1_kernel<<<g1_grid, g1_block, G1_SMEM>>>(x, W1);

    scan_kernel<<<1, 1024>>>();
    fill_kernel<<<(E + 255) / 256, 256>>>(edge_src, edge_dst, edge_val, E);

    int fw_grid = (N_NODES + FW_WARPS - 1) / FW_WARPS;
    fused_agg_gemm2_kernel<<<fw_grid, FW_WARPS * 32>>>(W2);

    spmm2_gather_kernel<<<fw_grid, FW_WARPS * 32>>>(out);
}

// round 5
// speedup vs baseline: 1.4379x; 1.4379x over previous
#include <cuda_runtime.h>
#include <cuda_bf16.h>

#define N_NODES 50000
#define E_MAX   800000
#define D_IN 128
#define D_H 96
#define D_OUT 32

#define SCAN_B 256
#define NBLK ((N_NODES + SCAN_B - 1) / SCAN_B)   // 196

// ---------------------------------------------------------------------------
// Scratch (__device__ globals; allocation-free rule)
// ---------------------------------------------------------------------------
__device__ float g_h1[N_NODES * D_H];       // x @ W1
__device__ float g_h2[N_NODES * D_OUT];     // relu(A@h1) @ W2
__device__ int   g_deg[N_NODES];            // degree counts / fill cursor
__device__ int   g_start[N_NODES + 1];      // CSR row starts (by dst)
__device__ int   g_excl[N_NODES];           // block-local exclusive prescan
__device__ int   g_bsum[NBLK];              // per-block sums
__device__ int   g_boff[NBLK];              // exclusive scan of block sums
__device__ int2  g_pair[E_MAX];             // per-edge {src, val_bits}, CSR order

// ---------------------------------------------------------------------------
// GEMM1: h1 = x @ W1   [50000,128]@[128,96]. Register tile 4 rows x 1 col.
// ---------------------------------------------------------------------------
#define G1_PAD  132
#define G1_ROWS 16
#define G1_ITER 4
#define G1_SMEM ((D_H * G1_PAD + G1_ROWS * G1_PAD) * sizeof(float))

__global__ void gemm1_kernel(const float* __restrict__ x,
                             const float* __restrict__ W1) {
    extern __shared__ float smem[];
    float* sWt = smem;                    // [96][132]  sWt[c][k] = W1[k][c]
    float* sx  = smem + D_H * G1_PAD;     // [16][132]

    const int tx = threadIdx.x, ty = threadIdx.y;
    const int t  = ty * 96 + tx;

    for (int i = t; i < D_IN * D_H; i += 384) {
        int k = i / D_H, c = i % D_H;
        sWt[c * G1_PAD + k] = W1[i];
    }
    __syncthreads();

    for (int it = 0; it < G1_ITER; it++) {
        int rowBase = (blockIdx.x * G1_ITER + it) * G1_ROWS;

        for (int i = t; i < G1_ROWS * D_IN; i += 384) {
            int r = i >> 7, k = i & 127;
            int row = rowBase + r;
            sx[r * G1_PAD + k] = (row < N_NODES) ? x[row * D_IN + k] : 0.f;
        }
        __syncthreads();

        float acc0 = 0.f, acc1 = 0.f, acc2 = 0.f, acc3 = 0.f;
        const float4* wrow = (const float4*)(sWt + tx * G1_PAD);
        const float4* xr0  = (const float4*)(sx + (ty * 4 + 0) * G1_PAD);
        const float4* xr1  = (const float4*)(sx + (ty * 4 + 1) * G1_PAD);
        const float4* xr2  = (const float4*)(sx + (ty * 4 + 2) * G1_PAD);
        const float4* xr3  = (const float4*)(sx + (ty * 4 + 3) * G1_PAD);

#pragma unroll
        for (int k4 = 0; k4 < D_IN / 4; k4++) {
            float4 w = wrow[k4];
            float4 v;
            v = xr0[k4]; acc0 = fmaf(v.x,w.x,fmaf(v.y,w.y,fmaf(v.z,w.z,fmaf(v.w,w.w,acc0))));
            v = xr1[k4]; acc1 = fmaf(v.x,w.x,fmaf(v.y,w.y,fmaf(v.z,w.z,fmaf(v.w,w.w,acc1))));
            v = xr2[k4]; acc2 = fmaf(v.x,w.x,fmaf(v.y,w.y,fmaf(v.z,w.z,fmaf(v.w,w.w,acc2))));
            v = xr3[k4]; acc3 = fmaf(v.x,w.x,fmaf(v.y,w.y,fmaf(v.z,w.z,fmaf(v.w,w.w,acc3))));
        }

        int r0 = rowBase + ty * 4;
        if (r0 + 0 < N_NODES) g_h1[(r0 + 0) * D_H + tx] = acc0;
        if (r0 + 1 < N_NODES) g_h1[(r0 + 1) * D_H + tx] = acc1;
        if (r0 + 2 < N_NODES) g_h1[(r0 + 2) * D_H + tx] = acc2;
        if (r0 + 3 < N_NODES) g_h1[(r0 + 3) * D_H + tx] = acc3;
        __syncthreads();
    }
}

// ---------------------------------------------------------------------------
// CSR build: zero -> count -> hierarchical scan (3 small kernels) -> fill
// ---------------------------------------------------------------------------
__global__ void zero_deg_kernel() {
    int i = blockIdx.x * blockDim.x + threadIdx.x;
    if (i < N_NODES) g_deg[i] = 0;
}

__global__ void count_kernel(const int* __restrict__ dst, int n_edges) {
    int e = blockIdx.x * blockDim.x + threadIdx.x;
    if (e < n_edges) atomicAdd(&g_deg[dst[e]], 1);
}

// Phase 1: per-block (256-wide) exclusive prescan of g_deg; block sums out.
__global__ void block_scan_kernel() {
    __shared__ int ws[8];
    int i = blockIdx.x * SCAN_B + threadIdx.x;
    int v = (i < N_NODES) ? g_deg[i] : 0;
    int lane = threadIdx.x & 31, wid = threadIdx.x >> 5;

    int inc = v;
#pragma unroll
    for (int off = 1; off < 32; off <<= 1) {
        int n = __shfl_up_sync(0xffffffffu, inc, off);
        if (lane >= off) inc += n;
    }
    if (lane == 31) ws[wid] = inc;
    __syncthreads();
    if (wid == 0) {
        int s = (lane < 8) ? ws[lane] : 0;
#pragma unroll
        for (int off = 1; off < 8; off <<= 1) {
            int n = __shfl_up_sync(0xffffffffu, s, off);
            if (lane >= off) s += n;
        }
        if (lane < 8) ws[lane] = s;
    }
    __syncthreads();

    int woff = (wid == 0) ? 0 : ws[wid - 1];
    if (i < N_NODES) g_excl[i] = woff + inc - v;
    if (threadIdx.x == SCAN_B - 1) g_bsum[blockIdx.x] = ws[7];
}

// Phase 2: exclusive scan of the NBLK (=196) block sums. One 256-thread block.
__global__ void scan_bsum_kernel() {
    __shared__ int ws[8];
    int t = threadIdx.x;
    int v = (t < NBLK) ? g_bsum[t] : 0;
    int lane = t & 31, wid = t >> 5;

    int inc = v;
#pragma unroll
    for (int off = 1; off < 32; off <<= 1) {
        int n = __shfl_up_sync(0xffffffffu, inc, off);
        if (lane >= off) inc += n;
    }
    if (lane == 31) ws[wid] = inc;
    __syncthreads();
    if (wid == 0) {
        int s = (lane < 8) ? ws[lane] : 0;
#pragma unroll
        for (int off = 1; off < 8; off <<= 1) {
            int n = __shfl_up_sync(0xffffffffu, s, off);
            if (lane >= off) s += n;
        }
        if (lane < 8) ws[lane] = s;
    }
    __syncthreads();

    int woff = (wid == 0) ? 0 : ws[wid - 1];
    if (t < NBLK) g_boff[t] = woff + inc - v;
}

// Phase 3: g_start[i] = g_excl[i] + g_boff[block]; reset cursor; set tail.
__global__ void finalize_start_kernel(int n_edges) {
    int i = blockIdx.x * SCAN_B + threadIdx.x;
    if (i < N_NODES) {
        g_start[i] = g_excl[i] + g_boff[blockIdx.x];
        g_deg[i] = 0;
    }
    if (i == 0) g_start[N_NODES] = n_edges;
}

__global__ void fill_kernel(const int* __restrict__ src,
                            const int* __restrict__ dst,
                            const float* __restrict__ val,
                            int n_edges) {
    int e = blockIdx.x * blockDim.x + threadIdx.x;
    if (e >= n_edges) return;
    int d = dst[e];
    int pos = g_start[d] + atomicAdd(&g_deg[d], 1);
    g_pair[pos] = make_int2(src[e], __float_as_int(val[e]));
}

// ---------------------------------------------------------------------------
// Fused layer 1 aggregation + relu + GEMM2:
//   h2[n] = relu( sum_{e in CSR[n]} val_e * h1[src_e] ) @ W2
// One warp per node. Lanes 0..23 gather float4 chunks (2-edge unroll for MLP);
// row staged in per-warp smem; lane c computes output col c against W2.
// ---------------------------------------------------------------------------
#define FW_WARPS 8
#define SROW_PAD 100

__global__ void fused_agg_gemm2_kernel(const float* __restrict__ W2) {
    __shared__ float sW2[D_H * D_OUT];              // [96][32], 12 KB
    __shared__ float srow[FW_WARPS][SROW_PAD];      // per-warp agg row

    int t = threadIdx.x;
    for (int i = t; i < D_H * D_OUT; i += blockDim.x) sW2[i] = W2[i];
    __syncthreads();

    int w    = t >> 5;
    int lane = t & 31;
    int n    = blockIdx.x * FW_WARPS + w;
    if (n >= N_NODES) return;

    int pBeg = g_start[n];
    int pEnd = g_start[n + 1];

    float ax = 0.f, ay = 0.f, az = 0.f, aw = 0.f;
    if (lane < 24) {
        int p = pBeg;
        for (; p + 1 < pEnd; p += 2) {
            int2 pa = g_pair[p];
            int2 pb = g_pair[p + 1];
            float4 ha = *reinterpret_cast<const float4*>(
                g_h1 + (long)pa.x * D_H + lane * 4);
            float4 hb = *reinterpret_cast<const float4*>(
                g_h1 + (long)pb.x * D_H + lane * 4);
            float va = __int_as_float(pa.y);
            float vb = __int_as_float(pb.y);
            ax = fmaf(va, ha.x, ax); ay = fmaf(va, ha.y, ay);
            az = fmaf(va, ha.z, az); aw = fmaf(va, ha.w, aw);
            ax = fmaf(vb, hb.x, ax); ay = fmaf(vb, hb.y, ay);
            az = fmaf(vb, hb.z, az); aw = fmaf(vb, hb.w, aw);
        }
        if (p < pEnd) {
            int2 pr = g_pair[p];
            float v = __int_as_float(pr.y);
            float4 h = *reinterpret_cast<const float4*>(
                g_h1 + (long)pr.x * D_H + lane * 4);
            ax = fmaf(v, h.x, ax); ay = fmaf(v, h.y, ay);
            az = fmaf(v, h.z, az); aw = fmaf(v, h.w, aw);
        }
        float4 r = make_float4(fmaxf(ax, 0.f), fmaxf(ay, 0.f),
                               fmaxf(az, 0.f), fmaxf(aw, 0.f));
        *reinterpret_cast<float4*>(&srow[w][lane * 4]) = r;
    }
    __syncwarp();

    // lane = output column; srow broadcast, sW2 conflict-free
    float acc = 0.f;
    const float4* sr4 = reinterpret_cast<const float4*>(&srow[w][0]);
#pragma unroll
    for (int k4 = 0; k4 < D_H / 4; k4++) {
        float4 s = sr4[k4];
        int k = k4 * 4;
        acc = fmaf(s.x, sW2[(k + 0) * D_OUT + lane], acc);
        acc = fmaf(s.y, sW2[(k + 1) * D_OUT + lane], acc);
        acc = fmaf(s.z, sW2[(k + 2) * D_OUT + lane], acc);
        acc = fmaf(s.w, sW2[(k + 3) * D_OUT + lane], acc);
    }
    g_h2[(long)n * D_OUT + lane] = acc;
}

// ---------------------------------------------------------------------------
// Layer 2 aggregation (gather): out[n] = sum val_e * h2[src_e]. One warp/node,
// lane = column (coalesced 128B gathers), 2-edge unroll for MLP.
// Writes every row (covers harness poison).
// ---------------------------------------------------------------------------
__global__ void spmm2_gather_kernel(float* __restrict__ out) {
    int t    = threadIdx.x;
    int w    = t >> 5;
    int lane = t & 31;
    int n    = blockIdx.x * FW_WARPS + w;
    if (n >= N_NODES) return;

    int pBeg = g_start[n];
    int pEnd = g_start[n + 1];

    float acc = 0.f;
    int p = pBeg;
    for (; p + 1 < pEnd; p += 2) {
        int2 pa = g_pair[p];
        int2 pb = g_pair[p + 1];
        float ha = g_h2[(long)pa.x * D_OUT + lane];
        float hb = g_h2[(long)pb.x * D_OUT + lane];
        acc = fmaf(__int_as_float(pa.y), ha, acc);
        acc = fmaf(__int_as_float(pb.y), hb, acc);
    }
    if (p < pEnd) {
        int2 pr = g_pair[p];
        acc = fmaf(__int_as_float(pr.y), g_h2[(long)pr.x * D_OUT + lane], acc);
    }
    out[(long)n * D_OUT + lane] = acc;
}

// ---------------------------------------------------------------------------
// Launch
// ---------------------------------------------------------------------------
extern "C" void kernel_launch(void* const* d_in, const int* in_sizes, int n_in,
                              void* d_out, int out_size) {
    const float* x        = (const float*)d_in[0];
    const int*   edge_src = (const int*)  d_in[1];
    const int*   edge_dst = (const int*)  d_in[2];
    const float* edge_val = (const float*)d_in[3];
    const float* W1       = (const float*)d_in[4];
    const float* W2       = (const float*)d_in[5];
    float*       out      = (float*)d_out;

    int E = in_sizes[1];

    cudaFuncSetAttribute(gemm1_kernel,
                         cudaFuncAttributeMaxDynamicSharedMemorySize,
                         (int)G1_SMEM);

    zero_deg_kernel<<<(N_NODES + 255) / 256, 256>>>();
    count_kernel<<<(E + 255) / 256, 256>>>(edge_dst, E);

    dim3 g1_block(96, 4);
    int  g1_grid = (N_NODES + G1_ROWS * G1_ITER - 1) / (G1_ROWS * G1_ITER);
    gemm1_kernel<<<g1_grid, g1_block, G1_SMEM>>>(x, W1);

    block_scan_kernel<<<NBLK, SCAN_B>>>();
    scan_bsum_kernel<<<1, 256>>>();
    finalize_start_kernel<<<NBLK, SCAN_B>>>(E);
    fill_kernel<<<(E + 255) / 256, 256>>>(edge_src, edge_dst, edge_val, E);

    int fw_grid = (N_NODES + FW_WARPS - 1) / FW_WARPS;
    fused_agg_gemm2_kernel<<<fw_grid, FW_WARPS * 32>>>(W2);

    spmm2_gather_kernel<<<fw_grid, FW_WARPS * 32>>>(out);
}

// round 8
// speedup vs baseline: 1.5227x; 1.0589x over previous
#include <cuda_runtime.h>
#include <cuda_bf16.h>

#define N_NODES 50000
#define E_MAX   800000
#define D_IN 128
#define D_H 96
#define D_OUT 32

#define SCAN_B 256
#define NBLK ((N_NODES + SCAN_B - 1) / SCAN_B)   // 196

// ---------------------------------------------------------------------------
// Scratch (__device__ globals; allocation-free rule)
// ---------------------------------------------------------------------------
__device__ float g_h1[N_NODES * D_H];       // x @ W1
__device__ float g_h2[N_NODES * D_OUT];     // relu(A@h1) @ W2
__device__ int   g_deg[N_NODES];            // degree counts / fill cursor
__device__ int   g_start[N_NODES + 1];      // CSR row starts (by dst)
__device__ int   g_excl[N_NODES];           // block-local exclusive prescan
__device__ int   g_bsum[NBLK];              // per-block sums
__device__ int   g_boff[NBLK];              // exclusive scan of block sums
__device__ int2  g_pair[E_MAX];             // per-edge {src, val_bits}, CSR order

// ---------------------------------------------------------------------------
// GEMM1: h1 = x @ W1   [50000,128]@[128,96].
// blockDim (96,4). Register tile: 8 rows x 1 col per thread ->
// 8 independent FFMA chains; per warp per 4-k step: 9 LDS.128 + 32 FFMA.
// ---------------------------------------------------------------------------
#define G1_PAD  132
#define G1_ROWS 32
#define G1_ITER 2
#define G1_SMEM ((D_H * G1_PAD + G1_ROWS * G1_PAD) * sizeof(float))

__global__ void gemm1_kernel(const float* __restrict__ x,
                             const float* __restrict__ W1) {
    extern __shared__ float smem[];
    float* sWt = smem;                    // [96][132]  sWt[c][k] = W1[k][c]
    float* sx  = smem + D_H * G1_PAD;     // [32][132]

    const int tx = threadIdx.x, ty = threadIdx.y;
    const int t  = ty * 96 + tx;

    for (int i = t; i < D_IN * D_H; i += 384) {
        int k = i / D_H, c = i % D_H;
        sWt[c * G1_PAD + k] = W1[i];
    }
    __syncthreads();

    for (int it = 0; it < G1_ITER; it++) {
        int rowBase = (blockIdx.x * G1_ITER + it) * G1_ROWS;

        for (int i = t; i < G1_ROWS * D_IN; i += 384) {
            int r = i >> 7, k = i & 127;
            int row = rowBase + r;
            sx[r * G1_PAD + k] = (row < N_NODES) ? x[row * D_IN + k] : 0.f;
        }
        __syncthreads();

        float acc[8];
        const float4* xr[8];
#pragma unroll
        for (int r = 0; r < 8; r++) {
            acc[r] = 0.f;
            xr[r] = (const float4*)(sx + (ty * 8 + r) * G1_PAD);
        }
        const float4* wrow = (const float4*)(sWt + tx * G1_PAD);

#pragma unroll 8
        for (int k4 = 0; k4 < D_IN / 4; k4++) {
            float4 w = wrow[k4];
#pragma unroll
            for (int r = 0; r < 8; r++) {
                float4 v = xr[r][k4];
                acc[r] = fmaf(v.x, w.x, fmaf(v.y, w.y,
                         fmaf(v.z, w.z, fmaf(v.w, w.w, acc[r]))));
            }
        }

        int r0 = rowBase + ty * 8;
#pragma unroll
        for (int r = 0; r < 8; r++)
            if (r0 + r < N_NODES) g_h1[(r0 + r) * D_H + tx] = acc[r];
        __syncthreads();
    }
}

// ---------------------------------------------------------------------------
// CSR build: zero -> count -> hierarchical scan (3 small kernels) -> fill
// ---------------------------------------------------------------------------
__global__ void zero_deg_kernel() {
    int i = blockIdx.x * blockDim.x + threadIdx.x;
    if (i < N_NODES) g_deg[i] = 0;
}

__global__ void count_kernel(const int* __restrict__ dst, int n_edges) {
    int e = blockIdx.x * blockDim.x + threadIdx.x;
    if (e < n_edges) atomicAdd(&g_deg[dst[e]], 1);
}

// Phase 1: per-block (256-wide) exclusive prescan of g_deg; block sums out.
__global__ void block_scan_kernel() {
    __shared__ int ws[8];
    int i = blockIdx.x * SCAN_B + threadIdx.x;
    int v = (i < N_NODES) ? g_deg[i] : 0;
    int lane = threadIdx.x & 31, wid = threadIdx.x >> 5;

    int inc = v;
#pragma unroll
    for (int off = 1; off < 32; off <<= 1) {
        int n = __shfl_up_sync(0xffffffffu, inc, off);
        if (lane >= off) inc += n;
    }
    if (lane == 31) ws[wid] = inc;
    __syncthreads();
    if (wid == 0) {
        int s = (lane < 8) ? ws[lane] : 0;
#pragma unroll
        for (int off = 1; off < 8; off <<= 1) {
            int n = __shfl_up_sync(0xffffffffu, s, off);
            if (lane >= off) s += n;
        }
        if (lane < 8) ws[lane] = s;
    }
    __syncthreads();

    int woff = (wid == 0) ? 0 : ws[wid - 1];
    if (i < N_NODES) g_excl[i] = woff + inc - v;
    if (threadIdx.x == SCAN_B - 1) g_bsum[blockIdx.x] = ws[7];
}

// Phase 2: exclusive scan of the NBLK (=196) block sums. One 256-thread block.
__global__ void scan_bsum_kernel() {
    __shared__ int ws[8];
    int t = threadIdx.x;
    int v = (t < NBLK) ? g_bsum[t] : 0;
    int lane = t & 31, wid = t >> 5;

    int inc = v;
#pragma unroll
    for (int off = 1; off < 32; off <<= 1) {
        int n = __shfl_up_sync(0xffffffffu, inc, off);
        if (lane >= off) inc += n;
    }
    if (lane == 31) ws[wid] = inc;
    __syncthreads();
    if (wid == 0) {
        int s = (lane < 8) ? ws[lane] : 0;
#pragma unroll
        for (int off = 1; off < 8; off <<= 1) {
            int n = __shfl_up_sync(0xffffffffu, s, off);
            if (lane >= off) s += n;
        }
        if (lane < 8) ws[lane] = s;
    }
    __syncthreads();

    int woff = (wid == 0) ? 0 : ws[wid - 1];
    if (t < NBLK) g_boff[t] = woff + inc - v;
}

// Phase 3: g_start[i] = g_excl[i] + g_boff[block]; reset cursor; set tail.
__global__ void finalize_start_kernel(int n_edges) {
    int i = blockIdx.x * SCAN_B + threadIdx.x;
    if (i < N_NODES) {
        g_start[i] = g_excl[i] + g_boff[blockIdx.x];
        g_deg[i] = 0;
    }
    if (i == 0) g_start[N_NODES] = n_edges;
}

__global__ void fill_kernel(const int* __restrict__ src,
                            const int* __restrict__ dst,
                            const float* __restrict__ val,
                            int n_edges) {
    int e = blockIdx.x * blockDim.x + threadIdx.x;
    if (e >= n_edges) return;
    int d = dst[e];
    int pos = g_start[d] + atomicAdd(&g_deg[d], 1);
    g_pair[pos] = make_int2(src[e], __float_as_int(val[e]));
}

// ---------------------------------------------------------------------------
// Fused layer 1 aggregation + relu + GEMM2:
//   h2[n] = relu( sum_{e in CSR[n]} val_e * h1[src_e] ) @ W2
// One warp per node. Lanes 0..23 gather float4 chunks (2-edge unroll);
// row staged in per-warp smem; lane c computes output col c against W2.
// ---------------------------------------------------------------------------
#define FW_WARPS 8
#define SROW_PAD 100

__global__ void fused_agg_gemm2_kernel(const float* __restrict__ W2) {
    __shared__ float sW2[D_H * D_OUT];              // [96][32], 12 KB
    __shared__ float srow[FW_WARPS][SROW_PAD];      // per-warp agg row

    int t = threadIdx.x;
    for (int i = t; i < D_H * D_OUT; i += blockDim.x) sW2[i] = W2[i];
    __syncthreads();

    int w    = t >> 5;
    int lane = t & 31;
    int n    = blockIdx.x * FW_WARPS + w;
    if (n >= N_NODES) return;

    int pBeg = g_start[n];
    int pEnd = g_start[n + 1];

    float ax = 0.f, ay = 0.f, az = 0.f, aw = 0.f;
    if (lane < 24) {
        int p = pBeg;
        for (; p + 1 < pEnd; p += 2) {
            int2 pa = g_pair[p];
            int2 pb = g_pair[p + 1];
            float4 ha = *reinterpret_cast<const float4*>(
                g_h1 + (long)pa.x * D_H + lane * 4);
            float4 hb = *reinterpret_cast<const float4*>(
                g_h1 + (long)pb.x * D_H + lane * 4);
            float va = __int_as_float(pa.y);
            float vb = __int_as_float(pb.y);
            ax = fmaf(va, ha.x, ax); ay = fmaf(va, ha.y, ay);
            az = fmaf(va, ha.z, az); aw = fmaf(va, ha.w, aw);
            ax = fmaf(vb, hb.x, ax); ay = fmaf(vb, hb.y, ay);
            az = fmaf(vb, hb.z, az); aw = fmaf(vb, hb.w, aw);
        }
        if (p < pEnd) {
            int2 pr = g_pair[p];
            float v = __int_as_float(pr.y);
            float4 h = *reinterpret_cast<const float4*>(
                g_h1 + (long)pr.x * D_H + lane * 4);
            ax = fmaf(v, h.x, ax); ay = fmaf(v, h.y, ay);
            az = fmaf(v, h.z, az); aw = fmaf(v, h.w, aw);
        }
        float4 r = make_float4(fmaxf(ax, 0.f), fmaxf(ay, 0.f),
                               fmaxf(az, 0.f), fmaxf(aw, 0.f));
        *reinterpret_cast<float4*>(&srow[w][lane * 4]) = r;
    }
    __syncwarp();

    // lane = output column; srow broadcast, sW2 conflict-free
    float acc = 0.f;
    const float4* sr4 = reinterpret_cast<const float4*>(&srow[w][0]);
#pragma unroll
    for (int k4 = 0; k4 < D_H / 4; k4++) {
        float4 s = sr4[k4];
        int k = k4 * 4;
        acc = fmaf(s.x, sW2[(k + 0) * D_OUT + lane], acc);
        acc = fmaf(s.y, sW2[(k + 1) * D_OUT + lane], acc);
        acc = fmaf(s.z, sW2[(k + 2) * D_OUT + lane], acc);
        acc = fmaf(s.w, sW2[(k + 3) * D_OUT + lane], acc);
    }
    g_h2[(long)n * D_OUT + lane] = acc;
}

// ---------------------------------------------------------------------------
// Layer 2 aggregation (gather): out[n] = sum val_e * h2[src_e]. One warp/node,
// lane = column (coalesced 128B gathers), 2-edge unroll.
// Writes every row (covers harness poison).
// ---------------------------------------------------------------------------
__global__ void spmm2_gather_kernel(float* __restrict__ out) {
    int t    = threadIdx.x;
    int w    = t >> 5;
    int lane = t & 31;
    int n    = blockIdx.x * FW_WARPS + w;
    if (n >= N_NODES) return;

    int pBeg = g_start[n];
    int pEnd = g_start[n + 1];

    float acc = 0.f;
    int p = pBeg;
    for (; p + 1 < pEnd; p += 2) {
        int2 pa = g_pair[p];
        int2 pb = g_pair[p + 1];
        float ha = g_h2[(long)pa.x * D_OUT + lane];
        float hb = g_h2[(long)pb.x * D_OUT + lane];
        acc = fmaf(__int_as_float(pa.y), ha, acc);
        acc = fmaf(__int_as_float(pb.y), hb, acc);
    }
    if (p < pEnd) {
        int2 pr = g_pair[p];
        acc = fmaf(__int_as_float(pr.y), g_h2[(long)pr.x * D_OUT + lane], acc);
    }
    out[(long)n * D_OUT + lane] = acc;
}

// ---------------------------------------------------------------------------
// Launch: single stream, serial (capture-safe; no stream/event creation).
// zero_deg -> count -> gemm1 -> scan x3 -> fill -> fused_agg -> spmm2
// ---------------------------------------------------------------------------
extern "C" void kernel_launch(void* const* d_in, const int* in_sizes, int n_in,
                              void* d_out, int out_size) {
    const float* x        = (const float*)d_in[0];
    const int*   edge_src = (const int*)  d_in[1];
    const int*   edge_dst = (const int*)  d_in[2];
    const float* edge_val = (const float*)d_in[3];
    const float* W1       = (const float*)d_in[4];
    const float* W2       = (const float*)d_in[5];
    float*       out      = (float*)d_out;

    int E = in_sizes[1];

    // One-time attribute set (hoisted out of capture path).
    static bool s_init = false;
    if (!s_init) {
        cudaFuncSetAttribute(gemm1_kernel,
                             cudaFuncAttributeMaxDynamicSharedMemorySize,
                             (int)G1_SMEM);
        s_init = true;
    }

    zero_deg_kernel<<<(N_NODES + 255) / 256, 256>>>();
    count_kernel<<<(E + 255) / 256, 256>>>(edge_dst, E);

    dim3 g1_block(96, 4);
    int  g1_grid = (N_NODES + G1_ROWS * G1_ITER - 1) / (G1_ROWS * G1_ITER);
    gemm1_kernel<<<g1_grid, g1_block, G1_SMEM>>>(x, W1);

    block_scan_kernel<<<NBLK, SCAN_B>>>();
    scan_bsum_kernel<<<1, 256>>>();
    finalize_start_kernel<<<NBLK, SCAN_B>>>(E);
    fill_kernel<<<(E + 255) / 256, 256>>>(edge_src, edge_dst, edge_val, E);

    int fw_grid = (N_NODES + FW_WARPS - 1) / FW_WARPS;
    fused_agg_gemm2_kernel<<<fw_grid, FW_WARPS * 32>>>(W2);

    spmm2_gather_kernel<<<fw_grid, FW_WARPS * 32>>>(out);
}

// round 9
// speedup vs baseline: 1.5419x; 1.0126x over previous
#include <cuda_runtime.h>
#include <cuda_bf16.h>

#define N_NODES 50000
#define E_MAX   800000
#define D_IN 128
#define D_H 96
#define D_OUT 32

#define SCAN_B 256
#define NBLK ((N_NODES + SCAN_B - 1) / SCAN_B)   // 196

// ---------------------------------------------------------------------------
// Scratch (__device__ globals; allocation-free rule)
// g_deg invariant: ZERO at entry of every launch (zero-init at load; fill's
// atomicSub returns it to zero each launch). No zeroing kernel needed.
// ---------------------------------------------------------------------------
__device__ float g_h1[N_NODES * D_H];       // x @ W1
__device__ float g_h2[N_NODES * D_OUT];     // relu(A@h1) @ W2
__device__ int   g_deg[N_NODES];            // degree counts / fill cursor
__device__ int   g_start[N_NODES + 1];      // CSR row starts (by dst)
__device__ int   g_excl[N_NODES];           // block-local exclusive prescan
__device__ int   g_bsum[NBLK];              // per-block sums
__device__ int2  g_pair[E_MAX];             // per-edge {src, val_bits}, CSR order

// ---------------------------------------------------------------------------
// GEMM1: h1 = x @ W1   [50000,128]@[128,96].
// blockDim (96,4). Register tile: 8 rows x 1 col per thread ->
// 8 independent FFMA chains; per warp per 4-k step: 9 LDS.128 + 32 FFMA.
// ---------------------------------------------------------------------------
#define G1_PAD  132
#define G1_ROWS 32
#define G1_ITER 2
#define G1_SMEM ((D_H * G1_PAD + G1_ROWS * G1_PAD) * sizeof(float))

__global__ void gemm1_kernel(const float* __restrict__ x,
                             const float* __restrict__ W1) {
    extern __shared__ float smem[];
    float* sWt = smem;                    // [96][132]  sWt[c][k] = W1[k][c]
    float* sx  = smem + D_H * G1_PAD;     // [32][132]

    const int tx = threadIdx.x, ty = threadIdx.y;
    const int t  = ty * 96 + tx;

    for (int i = t; i < D_IN * D_H; i += 384) {
        int k = i / D_H, c = i % D_H;
        sWt[c * G1_PAD + k] = W1[i];
    }
    __syncthreads();

    for (int it = 0; it < G1_ITER; it++) {
        int rowBase = (blockIdx.x * G1_ITER + it) * G1_ROWS;

        for (int i = t; i < G1_ROWS * D_IN; i += 384) {
            int r = i >> 7, k = i & 127;
            int row = rowBase + r;
            sx[r * G1_PAD + k] = (row < N_NODES) ? x[row * D_IN + k] : 0.f;
        }
        __syncthreads();

        float acc[8];
        const float4* xr[8];
#pragma unroll
        for (int r = 0; r < 8; r++) {
            acc[r] = 0.f;
            xr[r] = (const float4*)(sx + (ty * 8 + r) * G1_PAD);
        }
        const float4* wrow = (const float4*)(sWt + tx * G1_PAD);

#pragma unroll 8
        for (int k4 = 0; k4 < D_IN / 4; k4++) {
            float4 w = wrow[k4];
#pragma unroll
            for (int r = 0; r < 8; r++) {
                float4 v = xr[r][k4];
                acc[r] = fmaf(v.x, w.x, fmaf(v.y, w.y,
                         fmaf(v.z, w.z, fmaf(v.w, w.w, acc[r]))));
            }
        }

        int r0 = rowBase + ty * 8;
#pragma unroll
        for (int r = 0; r < 8; r++)
            if (r0 + r < N_NODES) g_h1[(r0 + r) * D_H + tx] = acc[r];
        __syncthreads();
    }
}

// ---------------------------------------------------------------------------
// CSR build: count -> block_scan -> finalize(w/ inline bsum reduce) -> fill
// ---------------------------------------------------------------------------
__global__ void count_kernel(const int* __restrict__ dst, int n_edges) {
    int e = blockIdx.x * blockDim.x + threadIdx.x;
    if (e < n_edges) atomicAdd(&g_deg[dst[e]], 1);
}

// Phase 1: per-block (256-wide) exclusive prescan of g_deg; block sums out.
__global__ void block_scan_kernel() {
    __shared__ int ws[8];
    int i = blockIdx.x * SCAN_B + threadIdx.x;
    int v = (i < N_NODES) ? g_deg[i] : 0;
    int lane = threadIdx.x & 31, wid = threadIdx.x >> 5;

    int inc = v;
#pragma unroll
    for (int off = 1; off < 32; off <<= 1) {
        int n = __shfl_up_sync(0xffffffffu, inc, off);
        if (lane >= off) inc += n;
    }
    if (lane == 31) ws[wid] = inc;
    __syncthreads();
    if (wid == 0) {
        int s = (lane < 8) ? ws[lane] : 0;
#pragma unroll
        for (int off = 1; off < 8; off <<= 1) {
            int n = __shfl_up_sync(0xffffffffu, s, off);
            if (lane >= off) s += n;
        }
        if (lane < 8) ws[lane] = s;
    }
    __syncthreads();

    int woff = (wid == 0) ? 0 : ws[wid - 1];
    if (i < N_NODES) g_excl[i] = woff + inc - v;
    if (threadIdx.x == SCAN_B - 1) g_bsum[blockIdx.x] = ws[7];
}

// Phase 2+3 fused: each block reduces g_bsum[0..bid) itself, then
// g_start[i] = g_excl[i] + boff. No g_deg reset needed (fill decrements).
__global__ void finalize_start_kernel(int n_edges) {
    __shared__ int sp[SCAN_B];
    int bid = blockIdx.x;
    int t = threadIdx.x;

    sp[t] = (t < bid && t < NBLK) ? g_bsum[t] : 0;
    __syncthreads();
#pragma unroll
    for (int off = SCAN_B / 2; off > 0; off >>= 1) {
        if (t < off) sp[t] += sp[t + off];
        __syncthreads();
    }
    int boff = sp[0];

    int i = bid * SCAN_B + t;
    if (i < N_NODES) g_start[i] = g_excl[i] + boff;
    if (i == 0) g_start[N_NODES] = n_edges;
}

// fill uses atomicSub: cursor runs deg -> 0, restoring the g_deg==0 invariant
// for the next launch/replay (slots start..start+deg-1, unique).
__global__ void fill_kernel(const int* __restrict__ src,
                            const int* __restrict__ dst,
                            const float* __restrict__ val,
                            int n_edges) {
    int e = blockIdx.x * blockDim.x + threadIdx.x;
    if (e >= n_edges) return;
    int d = dst[e];
    int pos = g_start[d] + atomicSub(&g_deg[d], 1) - 1;
    g_pair[pos] = make_int2(src[e], __float_as_int(val[e]));
}

// ---------------------------------------------------------------------------
// Fused layer 1 aggregation + relu + GEMM2:
//   h2[n] = relu( sum_{e in CSR[n]} val_e * h1[src_e] ) @ W2
// One warp per node, 16 warps/block (halves per-block sW2 reload traffic).
// Lanes 0..23 gather float4 chunks, 4-edge unroll for MLP; row staged in
// per-warp smem; lane c computes output col c against W2.
// ---------------------------------------------------------------------------
#define FW_WARPS 16
#define SROW_PAD 100

__global__ void fused_agg_gemm2_kernel(const float* __restrict__ W2) {
    __shared__ float sW2[D_H * D_OUT];              // [96][32], 12 KB
    __shared__ float srow[FW_WARPS][SROW_PAD];      // per-warp agg row

    int t = threadIdx.x;
    for (int i = t; i < D_H * D_OUT; i += blockDim.x) sW2[i] = W2[i];
    __syncthreads();

    int w    = t >> 5;
    int lane = t & 31;
    int n    = blockIdx.x * FW_WARPS + w;
    if (n >= N_NODES) return;

    const int2* __restrict__ pp = g_pair;
    int pBeg = g_start[n];
    int pEnd = g_start[n + 1];

    float ax = 0.f, ay = 0.f, az = 0.f, aw = 0.f;
    if (lane < 24) {
        int p = pBeg;
        for (; p + 3 < pEnd; p += 4) {
            int2 p0 = pp[p],     p1 = pp[p + 1];
            int2 p2 = pp[p + 2], p3 = pp[p + 3];
            float4 h0 = *reinterpret_cast<const float4*>(g_h1 + (long)p0.x * D_H + lane * 4);
            float4 h1 = *reinterpret_cast<const float4*>(g_h1 + (long)p1.x * D_H + lane * 4);
            float4 h2 = *reinterpret_cast<const float4*>(g_h1 + (long)p2.x * D_H + lane * 4);
            float4 h3 = *reinterpret_cast<const float4*>(g_h1 + (long)p3.x * D_H + lane * 4);
            float v0 = __int_as_float(p0.y), v1 = __int_as_float(p1.y);
            float v2 = __int_as_float(p2.y), v3 = __int_as_float(p3.y);
            ax = fmaf(v0, h0.x, ax); ay = fmaf(v0, h0.y, ay);
            az = fmaf(v0, h0.z, az); aw = fmaf(v0, h0.w, aw);
            ax = fmaf(v1, h1.x, ax); ay = fmaf(v1, h1.y, ay);
            az = fmaf(v1, h1.z, az); aw = fmaf(v1, h1.w, aw);
            ax = fmaf(v2, h2.x, ax); ay = fmaf(v2, h2.y, ay);
            az = fmaf(v2, h2.z, az); aw = fmaf(v2, h2.w, aw);
            ax = fmaf(v3, h3.x, ax); ay = fmaf(v3, h3.y, ay);
            az = fmaf(v3, h3.z, az); aw = fmaf(v3, h3.w, aw);
        }
        for (; p < pEnd; p++) {
            int2 pr = pp[p];
            float v = __int_as_float(pr.y);
            float4 h = *reinterpret_cast<const float4*>(g_h1 + (long)pr.x * D_H + lane * 4);
            ax = fmaf(v, h.x, ax); ay = fmaf(v, h.y, ay);
            az = fmaf(v, h.z, az); aw = fmaf(v, h.w, aw);
        }
        float4 r = make_float4(fmaxf(ax, 0.f), fmaxf(ay, 0.f),
                               fmaxf(az, 0.f), fmaxf(aw, 0.f));
        *reinterpret_cast<float4*>(&srow[w][lane * 4]) = r;
    }
    __syncwarp();

    // lane = output column; srow broadcast, sW2 conflict-free
    float acc = 0.f;
    const float4* sr4 = reinterpret_cast<const float4*>(&srow[w][0]);
#pragma unroll
    for (int k4 = 0; k4 < D_H / 4; k4++) {
        float4 s = sr4[k4];
        int k = k4 * 4;
        acc = fmaf(s.x, sW2[(k + 0) * D_OUT + lane], acc);
        acc = fmaf(s.y, sW2[(k + 1) * D_OUT + lane], acc);
        acc = fmaf(s.z, sW2[(k + 2) * D_OUT + lane], acc);
        acc = fmaf(s.w, sW2[(k + 3) * D_OUT + lane], acc);
    }
    g_h2[(long)n * D_OUT + lane] = acc;
}

// ---------------------------------------------------------------------------
// Layer 2 aggregation (gather): out[n] = sum val_e * h2[src_e]. One warp/node,
// lane = column (coalesced 128B gathers), 4-edge unroll.
// Writes every row (covers harness poison).
// ---------------------------------------------------------------------------
__global__ void spmm2_gather_kernel(float* __restrict__ out) {
    int t    = threadIdx.x;
    int w    = t >> 5;
    int lane = t & 31;
    int n    = blockIdx.x * FW_WARPS + w;
    if (n >= N_NODES) return;

    const int2* __restrict__ pp = g_pair;
    int pBeg = g_start[n];
    int pEnd = g_start[n + 1];

    float acc = 0.f;
    int p = pBeg;
    for (; p + 3 < pEnd; p += 4) {
        int2 p0 = pp[p],     p1 = pp[p + 1];
        int2 p2 = pp[p + 2], p3 = pp[p + 3];
        float h0 = g_h2[(long)p0.x * D_OUT + lane];
        float h1 = g_h2[(long)p1.x * D_OUT + lane];
        float h2 = g_h2[(long)p2.x * D_OUT + lane];
        float h3 = g_h2[(long)p3.x * D_OUT + lane];
        acc = fmaf(__int_as_float(p0.y), h0, acc);
        acc = fmaf(__int_as_float(p1.y), h1, acc);
        acc = fmaf(__int_as_float(p2.y), h2, acc);
        acc = fmaf(__int_as_float(p3.y), h3, acc);
    }
    for (; p < pEnd; p++) {
        int2 pr = pp[p];
        acc = fmaf(__int_as_float(pr.y), g_h2[(long)pr.x * D_OUT + lane], acc);
    }
    out[(long)n * D_OUT + lane] = acc;
}

// ---------------------------------------------------------------------------
// Launch: single stream, 7 kernels:
// count -> gemm1 -> block_scan -> finalize -> fill -> fused_agg -> spmm2
// ---------------------------------------------------------------------------
extern "C" void kernel_launch(void* const* d_in, const int* in_sizes, int n_in,
                              void* d_out, int out_size) {
    const float* x        = (const float*)d_in[0];
    const int*   edge_src = (const int*)  d_in[1];
    const int*   edge_dst = (const int*)  d_in[2];
    const float* edge_val = (const float*)d_in[3];
    const float* W1       = (const float*)d_in[4];
    const float* W2       = (const float*)d_in[5];
    float*       out      = (float*)d_out;

    int E = in_sizes[1];

    // One-time attribute set (hoisted out of capture path).
    static bool s_init = false;
    if (!s_init) {
        cudaFuncSetAttribute(gemm1_kernel,
                             cudaFuncAttributeMaxDynamicSharedMemorySize,
                             (int)G1_SMEM);
        s_init = true;
    }

    count_kernel<<<(E + 255) / 256, 256>>>(edge_dst, E);

    dim3 g1_block(96, 4);
    int  g1_grid = (N_NODES + G1_ROWS * G1_ITER - 1) / (G1_ROWS * G1_ITER);
    gemm1_kernel<<<g1_grid, g1_block, G1_SMEM>>>(x, W1);

    block_scan_kernel<<<NBLK, SCAN_B>>>();
    finalize_start_kernel<<<NBLK, SCAN_B>>>(E);
    fill_kernel<<<(E + 255) / 256, 256>>>(edge_src, edge_dst, edge_val, E);

    int fw_grid = (N_NODES + FW_WARPS - 1) / FW_WARPS;
    fused_agg_gemm2_kernel<<<fw_grid, FW_WARPS * 32>>>(W2);

    spmm2_gather_kernel<<<fw_grid, FW_WARPS * 32>>>(out);
}

// round 11
// speedup vs baseline: 1.6410x; 1.0643x over previous
#include <cuda_runtime.h>
#include <cuda_bf16.h>

#define N_NODES 50000
#define E_MAX   800000
#define D_IN 128
#define D_H 96
#define D_OUT 32

#define SCAN_B 256
#define NBLK ((N_NODES + SCAN_B - 1) / SCAN_B)   // 196

// ---------------------------------------------------------------------------
// Scratch (__device__ globals; allocation-free rule)
// g_deg invariant: ZERO at entry of every launch (zero-init at load; fill's
// atomicSub returns it to zero each launch). No zeroing kernel needed.
// ---------------------------------------------------------------------------
__device__ __nv_bfloat16 g_h1b[N_NODES * D_H];  // x @ W1, bf16 (halves gather B/W)
__device__ float g_h2[N_NODES * D_OUT];         // relu(A@h1) @ W2
__device__ int   g_deg[N_NODES];                // degree counts / fill cursor
__device__ int   g_start[N_NODES + 1];          // CSR row starts (by dst)
__device__ int   g_excl[N_NODES];               // block-local exclusive prescan
__device__ int   g_bsum[NBLK];                  // per-block sums
__device__ int2  g_pair[E_MAX];                 // per-edge {src, val_bits}

// ---------------------------------------------------------------------------
// GEMM1: h1 = x @ W1   [50000,128]@[128,96], fp32 math, bf16 store.
// blockDim (96,4). Register tile: 8 rows x 1 col per thread.
// ---------------------------------------------------------------------------
#define G1_PAD  132
#define G1_ROWS 32
#define G1_ITER 2
#define G1_SMEM ((D_H * G1_PAD + G1_ROWS * G1_PAD) * sizeof(float))

__global__ void gemm1_kernel(const float* __restrict__ x,
                             const float* __restrict__ W1) {
    extern __shared__ float smem[];
    float* sWt = smem;                    // [96][132]  sWt[c][k] = W1[k][c]
    float* sx  = smem + D_H * G1_PAD;     // [32][132]

    const int tx = threadIdx.x, ty = threadIdx.y;
    const int t  = ty * 96 + tx;

    for (int i = t; i < D_IN * D_H; i += 384) {
        int k = i / D_H, c = i % D_H;
        sWt[c * G1_PAD + k] = W1[i];
    }
    __syncthreads();

    for (int it = 0; it < G1_ITER; it++) {
        int rowBase = (blockIdx.x * G1_ITER + it) * G1_ROWS;

        for (int i = t; i < G1_ROWS * D_IN; i += 384) {
            int r = i >> 7, k = i & 127;
            int row = rowBase + r;
            sx[r * G1_PAD + k] = (row < N_NODES) ? x[row * D_IN + k] : 0.f;
        }
        __syncthreads();

        float acc[8];
        const float4* xr[8];
#pragma unroll
        for (int r = 0; r < 8; r++) {
            acc[r] = 0.f;
            xr[r] = (const float4*)(sx + (ty * 8 + r) * G1_PAD);
        }
        const float4* wrow = (const float4*)(sWt + tx * G1_PAD);

#pragma unroll 8
        for (int k4 = 0; k4 < D_IN / 4; k4++) {
            float4 w = wrow[k4];
#pragma unroll
            for (int r = 0; r < 8; r++) {
                float4 v = xr[r][k4];
                acc[r] = fmaf(v.x, w.x, fmaf(v.y, w.y,
                         fmaf(v.z, w.z, fmaf(v.w, w.w, acc[r]))));
            }
        }

        int r0 = rowBase + ty * 8;
#pragma unroll
        for (int r = 0; r < 8; r++)
            if (r0 + r < N_NODES)
                g_h1b[(r0 + r) * D_H + tx] = __float2bfloat16_rn(acc[r]);
        __syncthreads();
    }
}

// ---------------------------------------------------------------------------
// CSR build: count -> block_scan -> finalize(w/ inline bsum reduce) -> fill
// ---------------------------------------------------------------------------
__global__ void count_kernel(const int* __restrict__ dst, int n_edges) {
    int e = blockIdx.x * blockDim.x + threadIdx.x;
    if (e < n_edges) atomicAdd(&g_deg[dst[e]], 1);
}

__global__ void block_scan_kernel() {
    __shared__ int ws[8];
    int i = blockIdx.x * SCAN_B + threadIdx.x;
    int v = (i < N_NODES) ? g_deg[i] : 0;
    int lane = threadIdx.x & 31, wid = threadIdx.x >> 5;

    int inc = v;
#pragma unroll
    for (int off = 1; off < 32; off <<= 1) {
        int n = __shfl_up_sync(0xffffffffu, inc, off);
        if (lane >= off) inc += n;
    }
    if (lane == 31) ws[wid] = inc;
    __syncthreads();
    if (wid == 0) {
        int s = (lane < 8) ? ws[lane] : 0;
#pragma unroll
        for (int off = 1; off < 8; off <<= 1) {
            int n = __shfl_up_sync(0xffffffffu, s, off);
            if (lane >= off) s += n;
        }
        if (lane < 8) ws[lane] = s;
    }
    __syncthreads();

    int woff = (wid == 0) ? 0 : ws[wid - 1];
    if (i < N_NODES) g_excl[i] = woff + inc - v;
    if (threadIdx.x == SCAN_B - 1) g_bsum[blockIdx.x] = ws[7];
}

__global__ void finalize_start_kernel(int n_edges) {
    __shared__ int sp[SCAN_B];
    int bid = blockIdx.x;
    int t = threadIdx.x;

    sp[t] = (t < bid && t < NBLK) ? g_bsum[t] : 0;
    __syncthreads();
#pragma unroll
    for (int off = SCAN_B / 2; off > 0; off >>= 1) {
        if (t < off) sp[t] += sp[t + off];
        __syncthreads();
    }
    int boff = sp[0];

    int i = bid * SCAN_B + t;
    if (i < N_NODES) g_start[i] = g_excl[i] + boff;
    if (i == 0) g_start[N_NODES] = n_edges;
}

// fill uses atomicSub: cursor runs deg -> 0, restoring the g_deg==0 invariant.
__global__ void fill_kernel(const int* __restrict__ src,
                            const int* __restrict__ dst,
                            const float* __restrict__ val,
                            int n_edges) {
    int e = blockIdx.x * blockDim.x + threadIdx.x;
    if (e >= n_edges) return;
    int d = dst[e];
    int pos = g_start[d] + atomicSub(&g_deg[d], 1) - 1;
    g_pair[pos] = make_int2(src[e], __float_as_int(val[e]));
}

// ---------------------------------------------------------------------------
// Fused layer 1 aggregation + relu + GEMM2 (bf16 h1 gathers):
//   h2[n] = relu( sum_e val_e * h1[src_e] ) @ W2
// One warp per node, 32 warps/block (sW2 loaded once per 32 nodes).
// Lanes 0..23 each gather 8B (4 bf16 feats) per edge, 4-edge unroll.
// ---------------------------------------------------------------------------
#define FW_WARPS 32
#define SROW_PAD 100

__device__ __forceinline__ void bf16x4_fma(uint2 raw, float v,
                                           float& ax, float& ay,
                                           float& az, float& aw) {
    float2 f0 = __bfloat1622float2(*reinterpret_cast<const __nv_bfloat162*>(&raw.x));
    float2 f1 = __bfloat1622float2(*reinterpret_cast<const __nv_bfloat162*>(&raw.y));
    ax = fmaf(v, f0.x, ax); ay = fmaf(v, f0.y, ay);
    az = fmaf(v, f1.x, az); aw = fmaf(v, f1.y, aw);
}

__global__ void __launch_bounds__(FW_WARPS * 32)
fused_agg_gemm2_kernel(const float* __restrict__ W2) {
    __shared__ float sW2[D_H * D_OUT];              // [96][32], 12 KB
    __shared__ float srow[FW_WARPS][SROW_PAD];      // per-warp agg row, 12.8 KB

    int t = threadIdx.x;
    for (int i = t; i < D_H * D_OUT; i += blockDim.x) sW2[i] = W2[i];
    __syncthreads();

    int w    = t >> 5;
    int lane = t & 31;
    int n    = blockIdx.x * FW_WARPS + w;
    if (n >= N_NODES) return;

    const int2* __restrict__ pp = g_pair;
    int pBeg = g_start[n];
    int pEnd = g_start[n + 1];

    float ax = 0.f, ay = 0.f, az = 0.f, aw = 0.f;
    if (lane < 24) {
        int p = pBeg;
        for (; p + 3 < pEnd; p += 4) {
            int2 p0 = pp[p],     p1 = pp[p + 1];
            int2 p2 = pp[p + 2], p3 = pp[p + 3];
            uint2 r0 = *reinterpret_cast<const uint2*>(g_h1b + (long)p0.x * D_H + lane * 4);
            uint2 r1 = *reinterpret_cast<const uint2*>(g_h1b + (long)p1.x * D_H + lane * 4);
            uint2 r2 = *reinterpret_cast<const uint2*>(g_h1b + (long)p2.x * D_H + lane * 4);
            uint2 r3 = *reinterpret_cast<const uint2*>(g_h1b + (long)p3.x * D_H + lane * 4);
            bf16x4_fma(r0, __int_as_float(p0.y), ax, ay, az, aw);
            bf16x4_fma(r1, __int_as_float(p1.y), ax, ay, az, aw);
            bf16x4_fma(r2, __int_as_float(p2.y), ax, ay, az, aw);
            bf16x4_fma(r3, __int_as_float(p3.y), ax, ay, az, aw);
        }
        for (; p < pEnd; p++) {
            int2 pr = pp[p];
            uint2 r = *reinterpret_cast<const uint2*>(g_h1b + (long)pr.x * D_H + lane * 4);
            bf16x4_fma(r, __int_as_float(pr.y), ax, ay, az, aw);
        }
        float4 r = make_float4(fmaxf(ax, 0.f), fmaxf(ay, 0.f),
                               fmaxf(az, 0.f), fmaxf(aw, 0.f));
        *reinterpret_cast<float4*>(&srow[w][lane * 4]) = r;
    }
    __syncwarp();

    // lane = output column; srow broadcast, sW2 conflict-free
    float acc = 0.f;
    const float4* sr4 = reinterpret_cast<const float4*>(&srow[w][0]);
#pragma unroll
    for (int k4 = 0; k4 < D_H / 4; k4++) {
        float4 s = sr4[k4];
        int k = k4 * 4;
        acc = fmaf(s.x, sW2[(k + 0) * D_OUT + lane], acc);
        acc = fmaf(s.y, sW2[(k + 1) * D_OUT + lane], acc);
        acc = fmaf(s.z, sW2[(k + 2) * D_OUT + lane], acc);
        acc = fmaf(s.w, sW2[(k + 3) * D_OUT + lane], acc);
    }
    g_h2[(long)n * D_OUT + lane] = acc;
}

// ---------------------------------------------------------------------------
// Layer 2 aggregation (gather): out[n] = sum val_e * h2[src_e]. One warp/node,
// lane = column (coalesced 128B gathers), 4-edge unroll. fp32 throughout.
// ---------------------------------------------------------------------------
__global__ void __launch_bounds__(FW_WARPS * 32)
spmm2_gather_kernel(float* __restrict__ out) {
    int t    = threadIdx.x;
    int w    = t >> 5;
    int lane = t & 31;
    int n    = blockIdx.x * FW_WARPS + w;
    if (n >= N_NODES) return;

    const int2* __restrict__ pp = g_pair;
    int pBeg = g_start[n];
    int pEnd = g_start[n + 1];

    float acc = 0.f;
    int p = pBeg;
    for (; p + 3 < pEnd; p += 4) {
        int2 p0 = pp[p],     p1 = pp[p + 1];
        int2 p2 = pp[p + 2], p3 = pp[p + 3];
        float h0 = g_h2[(long)p0.x * D_OUT + lane];
        float h1 = g_h2[(long)p1.x * D_OUT + lane];
        float h2 = g_h2[(long)p2.x * D_OUT + lane];
        float h3 = g_h2[(long)p3.x * D_OUT + lane];
        acc = fmaf(__int_as_float(p0.y), h0, acc);
        acc = fmaf(__int_as_float(p1.y), h1, acc);
        acc = fmaf(__int_as_float(p2.y), h2, acc);
        acc = fmaf(__int_as_float(p3.y), h3, acc);
    }
    for (; p < pEnd; p++) {
        int2 pr = pp[p];
        acc = fmaf(__int_as_float(pr.y), g_h2[(long)pr.x * D_OUT + lane], acc);
    }
    out[(long)n * D_OUT + lane] = acc;
}

// ---------------------------------------------------------------------------
// Launch: single stream, 7 kernels:
// count -> gemm1 -> block_scan -> finalize -> fill -> fused_agg -> spmm2
// ---------------------------------------------------------------------------
extern "C" void kernel_launch(void* const* d_in, const int* in_sizes, int n_in,
                              void* d_out, int out_size) {
    const float* x        = (const float*)d_in[0];
    const int*   edge_src = (const int*)  d_in[1];
    const int*   edge_dst = (const int*)  d_in[2];
    const float* edge_val = (const float*)d_in[3];
    const float* W1       = (const float*)d_in[4];
    const float* W2       = (const float*)d_in[5];
    float*       out      = (float*)d_out;

    int E = in_sizes[1];

    static bool s_init = false;
    if (!s_init) {
        cudaFuncSetAttribute(gemm1_kernel,
                             cudaFuncAttributeMaxDynamicSharedMemorySize,
                             (int)G1_SMEM);
        s_init = true;
    }

    count_kernel<<<(E + 255) / 256, 256>>>(edge_dst, E);

    dim3 g1_block(96, 4);
    int  g1_grid = (N_NODES + G1_ROWS * G1_ITER - 1) / (G1_ROWS * G1_ITER);
    gemm1_kernel<<<g1_grid, g1_block, G1_SMEM>>>(x, W1);

    block_scan_kernel<<<NBLK, SCAN_B>>>();
    finalize_start_kernel<<<NBLK, SCAN_B>>>(E);
    fill_kernel<<<(E + 255) / 256, 256>>>(edge_src, edge_dst, edge_val, E);

    int fw_grid = (N_NODES + FW_WARPS - 1) / FW_WARPS;
    fused_agg_gemm2_kernel<<<fw_grid, FW_WARPS * 32>>>(W2);

    spmm2_gather_kernel<<<fw_grid, FW_WARPS * 32>>>(out);
}

// round 12
// speedup vs baseline: 1.6749x; 1.0207x over previous
#include <cuda_runtime.h>
#include <cuda_fp16.h>

#define N_NODES 50000
#define E_MAX   800000
#define D_IN 128
#define D_H 96
#define D_OUT 32

#define SCAN_B 256
#define NBLK ((N_NODES + SCAN_B - 1) / SCAN_B)   // 196

// ---------------------------------------------------------------------------
// Scratch (__device__ globals; allocation-free rule)
// g_deg invariant: ZERO at entry of every launch (zero-init at load; fill's
// atomicSub returns it to zero each launch). No zeroing kernel needed.
// fp16 (not bf16): same 2B/elem gather cost, 8x finer mantissa. Value ranges
// (|h1| < ~8, |h2| < ~16) are far inside fp16 range.
// ---------------------------------------------------------------------------
__device__ __half g_h1h[N_NODES * D_H];     // x @ W1, fp16
__device__ __half g_h2h[N_NODES * D_OUT];   // relu(A@h1) @ W2, fp16
__device__ int    g_deg[N_NODES];           // degree counts / fill cursor
__device__ int    g_start[N_NODES + 1];     // CSR row starts (by dst)
__device__ int    g_excl[N_NODES];          // block-local exclusive prescan
__device__ int    g_bsum[NBLK];             // per-block sums
__device__ int2   g_pair[E_MAX];            // per-edge {src, val_bits}

// ---------------------------------------------------------------------------
// GEMM1: h1 = x @ W1   [50000,128]@[128,96], fp32 math, fp16 store.
// blockDim (96,4). Register tile: 8 rows x 1 col per thread.
// ---------------------------------------------------------------------------
#define G1_PAD  132
#define G1_ROWS 32
#define G1_ITER 2
#define G1_SMEM ((D_H * G1_PAD + G1_ROWS * G1_PAD) * sizeof(float))

__global__ void gemm1_kernel(const float* __restrict__ x,
                             const float* __restrict__ W1) {
    extern __shared__ float smem[];
    float* sWt = smem;                    // [96][132]  sWt[c][k] = W1[k][c]
    float* sx  = smem + D_H * G1_PAD;     // [32][132]

    const int tx = threadIdx.x, ty = threadIdx.y;
    const int t  = ty * 96 + tx;

    for (int i = t; i < D_IN * D_H; i += 384) {
        int k = i / D_H, c = i % D_H;
        sWt[c * G1_PAD + k] = W1[i];
    }
    __syncthreads();

    for (int it = 0; it < G1_ITER; it++) {
        int rowBase = (blockIdx.x * G1_ITER + it) * G1_ROWS;

        for (int i = t; i < G1_ROWS * D_IN; i += 384) {
            int r = i >> 7, k = i & 127;
            int row = rowBase + r;
            sx[r * G1_PAD + k] = (row < N_NODES) ? x[row * D_IN + k] : 0.f;
        }
        __syncthreads();

        float acc[8];
        const float4* xr[8];
#pragma unroll
        for (int r = 0; r < 8; r++) {
            acc[r] = 0.f;
            xr[r] = (const float4*)(sx + (ty * 8 + r) * G1_PAD);
        }
        const float4* wrow = (const float4*)(sWt + tx * G1_PAD);

#pragma unroll 8
        for (int k4 = 0; k4 < D_IN / 4; k4++) {
            float4 w = wrow[k4];
#pragma unroll
            for (int r = 0; r < 8; r++) {
                float4 v = xr[r][k4];
                acc[r] = fmaf(v.x, w.x, fmaf(v.y, w.y,
                         fmaf(v.z, w.z, fmaf(v.w, w.w, acc[r]))));
            }
        }

        int r0 = rowBase + ty * 8;
#pragma unroll
        for (int r = 0; r < 8; r++)
            if (r0 + r < N_NODES)
                g_h1h[(r0 + r) * D_H + tx] = __float2half_rn(acc[r]);
        __syncthreads();
    }
}

// ---------------------------------------------------------------------------
// CSR build: count -> block_scan -> finalize(w/ inline bsum reduce) -> fill
// ---------------------------------------------------------------------------
__global__ void count_kernel(const int* __restrict__ dst, int n_edges) {
    int e = blockIdx.x * blockDim.x + threadIdx.x;
    if (e < n_edges) atomicAdd(&g_deg[dst[e]], 1);
}

__global__ void block_scan_kernel() {
    __shared__ int ws[8];
    int i = blockIdx.x * SCAN_B + threadIdx.x;
    int v = (i < N_NODES) ? g_deg[i] : 0;
    int lane = threadIdx.x & 31, wid = threadIdx.x >> 5;

    int inc = v;
#pragma unroll
    for (int off = 1; off < 32; off <<= 1) {
        int n = __shfl_up_sync(0xffffffffu, inc, off);
        if (lane >= off) inc += n;
    }
    if (lane == 31) ws[wid] = inc;
    __syncthreads();
    if (wid == 0) {
        int s = (lane < 8) ? ws[lane] : 0;
#pragma unroll
        for (int off = 1; off < 8; off <<= 1) {
            int n = __shfl_up_sync(0xffffffffu, s, off);
            if (lane >= off) s += n;
        }
        if (lane < 8) ws[lane] = s;
    }
    __syncthreads();

    int woff = (wid == 0) ? 0 : ws[wid - 1];
    if (i < N_NODES) g_excl[i] = woff + inc - v;
    if (threadIdx.x == SCAN_B - 1) g_bsum[blockIdx.x] = ws[7];
}

__global__ void finalize_start_kernel(int n_edges) {
    __shared__ int sp[SCAN_B];
    int bid = blockIdx.x;
    int t = threadIdx.x;

    sp[t] = (t < bid && t < NBLK) ? g_bsum[t] : 0;
    __syncthreads();
#pragma unroll
    for (int off = SCAN_B / 2; off > 0; off >>= 1) {
        if (t < off) sp[t] += sp[t + off];
        __syncthreads();
    }
    int boff = sp[0];

    int i = bid * SCAN_B + t;
    if (i < N_NODES) g_start[i] = g_excl[i] + boff;
    if (i == 0) g_start[N_NODES] = n_edges;
}

// fill uses atomicSub: cursor runs deg -> 0, restoring the g_deg==0 invariant.
__global__ void fill_kernel(const int* __restrict__ src,
                            const int* __restrict__ dst,
                            const float* __restrict__ val,
                            int n_edges) {
    int e = blockIdx.x * blockDim.x + threadIdx.x;
    if (e >= n_edges) return;
    int d = dst[e];
    int pos = g_start[d] + atomicSub(&g_deg[d], 1) - 1;
    g_pair[pos] = make_int2(src[e], __float_as_int(val[e]));
}

// ---------------------------------------------------------------------------
// Fused layer 1 aggregation + relu + GEMM2 (fp16 h1 gathers, fp32 accum):
//   h2[n] = relu( sum_e val_e * h1[src_e] ) @ W2
// One warp per node, 32 warps/block (sW2 loaded once per 32 nodes).
// Lanes 0..23 each gather 8B (4 fp16 feats) per edge, 4-edge unroll.
// ---------------------------------------------------------------------------
#define FW_WARPS 32
#define SROW_PAD 100

__device__ __forceinline__ void f16x4_fma(uint2 raw, float v,
                                          float& ax, float& ay,
                                          float& az, float& aw) {
    float2 f0 = __half22float2(*reinterpret_cast<const __half2*>(&raw.x));
    float2 f1 = __half22float2(*reinterpret_cast<const __half2*>(&raw.y));
    ax = fmaf(v, f0.x, ax); ay = fmaf(v, f0.y, ay);
    az = fmaf(v, f1.x, az); aw = fmaf(v, f1.y, aw);
}

__global__ void __launch_bounds__(FW_WARPS * 32)
fused_agg_gemm2_kernel(const float* __restrict__ W2) {
    __shared__ float sW2[D_H * D_OUT];              // [96][32], 12 KB
    __shared__ float srow[FW_WARPS][SROW_PAD];      // per-warp agg row, 12.8 KB

    int t = threadIdx.x;
    for (int i = t; i < D_H * D_OUT; i += blockDim.x) sW2[i] = W2[i];
    __syncthreads();

    int w    = t >> 5;
    int lane = t & 31;
    int n    = blockIdx.x * FW_WARPS + w;
    if (n >= N_NODES) return;

    const int2* __restrict__ pp = g_pair;
    int pBeg = g_start[n];
    int pEnd = g_start[n + 1];

    float ax = 0.f, ay = 0.f, az = 0.f, aw = 0.f;
    if (lane < 24) {
        int p = pBeg;
        for (; p + 3 < pEnd; p += 4) {
            int2 p0 = pp[p],     p1 = pp[p + 1];
            int2 p2 = pp[p + 2], p3 = pp[p + 3];
            uint2 r0 = *reinterpret_cast<const uint2*>(g_h1h + (long)p0.x * D_H + lane * 4);
            uint2 r1 = *reinterpret_cast<const uint2*>(g_h1h + (long)p1.x * D_H + lane * 4);
            uint2 r2 = *reinterpret_cast<const uint2*>(g_h1h + (long)p2.x * D_H + lane * 4);
            uint2 r3 = *reinterpret_cast<const uint2*>(g_h1h + (long)p3.x * D_H + lane * 4);
            f16x4_fma(r0, __int_as_float(p0.y), ax, ay, az, aw);
            f16x4_fma(r1, __int_as_float(p1.y), ax, ay, az, aw);
            f16x4_fma(r2, __int_as_float(p2.y), ax, ay, az, aw);
            f16x4_fma(r3, __int_as_float(p3.y), ax, ay, az, aw);
        }
        for (; p < pEnd; p++) {
            int2 pr = pp[p];
            uint2 r = *reinterpret_cast<const uint2*>(g_h1h + (long)pr.x * D_H + lane * 4);
            f16x4_fma(r, __int_as_float(pr.y), ax, ay, az, aw);
        }
        float4 r = make_float4(fmaxf(ax, 0.f), fmaxf(ay, 0.f),
                               fmaxf(az, 0.f), fmaxf(aw, 0.f));
        *reinterpret_cast<float4*>(&srow[w][lane * 4]) = r;
    }
    __syncwarp();

    // lane = output column; srow broadcast, sW2 conflict-free; fp16 store
    float acc = 0.f;
    const float4* sr4 = reinterpret_cast<const float4*>(&srow[w][0]);
#pragma unroll
    for (int k4 = 0; k4 < D_H / 4; k4++) {
        float4 s = sr4[k4];
        int k = k4 * 4;
        acc = fmaf(s.x, sW2[(k + 0) * D_OUT + lane], acc);
        acc = fmaf(s.y, sW2[(k + 1) * D_OUT + lane], acc);
        acc = fmaf(s.z, sW2[(k + 2) * D_OUT + lane], acc);
        acc = fmaf(s.w, sW2[(k + 3) * D_OUT + lane], acc);
    }
    g_h2h[(long)n * D_OUT + lane] = __float2half_rn(acc);
}

// ---------------------------------------------------------------------------
// Layer 2 aggregation (gather): out[n] = sum val_e * h2[src_e]. One warp/node,
// lane = column (coalesced 64B fp16 gathers), 4-edge unroll, fp32 accum.
// Writes every row (covers harness poison).
// ---------------------------------------------------------------------------
__global__ void __launch_bounds__(FW_WARPS * 32)
spmm2_gather_kernel(float* __restrict__ out) {
    int t    = threadIdx.x;
    int w    = t >> 5;
    int lane = t & 31;
    int n    = blockIdx.x * FW_WARPS + w;
    if (n >= N_NODES) return;

    const int2* __restrict__ pp = g_pair;
    int pBeg = g_start[n];
    int pEnd = g_start[n + 1];

    float acc = 0.f;
    int p = pBeg;
    for (; p + 3 < pEnd; p += 4) {
        int2 p0 = pp[p],     p1 = pp[p + 1];
        int2 p2 = pp[p + 2], p3 = pp[p + 3];
        float h0 = __half2float(g_h2h[(long)p0.x * D_OUT + lane]);
        float h1 = __half2float(g_h2h[(long)p1.x * D_OUT + lane]);
        float h2 = __half2float(g_h2h[(long)p2.x * D_OUT + lane]);
        float h3 = __half2float(g_h2h[(long)p3.x * D_OUT + lane]);
        acc = fmaf(__int_as_float(p0.y), h0, acc);
        acc = fmaf(__int_as_float(p1.y), h1, acc);
        acc = fmaf(__int_as_float(p2.y), h2, acc);
        acc = fmaf(__int_as_float(p3.y), h3, acc);
    }
    for (; p < pEnd; p++) {
        int2 pr = pp[p];
        acc = fmaf(__int_as_float(pr.y),
                   __half2float(g_h2h[(long)pr.x * D_OUT + lane]), acc);
    }
    out[(long)n * D_OUT + lane] = acc;
}

// ---------------------------------------------------------------------------
// Launch: single stream, 7 kernels:
// count -> gemm1 -> block_scan -> finalize -> fill -> fused_agg -> spmm2
// ---------------------------------------------------------------------------
extern "C" void kernel_launch(void* const* d_in, const int* in_sizes, int n_in,
                              void* d_out, int out_size) {
    const float* x        = (const float*)d_in[0];
    const int*   edge_src = (const int*)  d_in[1];
    const int*   edge_dst = (const int*)  d_in[2];
    const float* edge_val = (const float*)d_in[3];
    const float* W1       = (const float*)d_in[4];
    const float* W2       = (const float*)d_in[5];
    float*       out      = (float*)d_out;

    int E = in_sizes[1];

    static bool s_init = false;
    if (!s_init) {
        cudaFuncSetAttribute(gemm1_kernel,
                             cudaFuncAttributeMaxDynamicSharedMemorySize,
                             (int)G1_SMEM);
        s_init = true;
    }

    count_kernel<<<(E + 255) / 256, 256>>>(edge_dst, E);

    dim3 g1_block(96, 4);
    int  g1_grid = (N_NODES + G1_ROWS * G1_ITER - 1) / (G1_ROWS * G1_ITER);
    gemm1_kernel<<<g1_grid, g1_block, G1_SMEM>>>(x, W1);

    block_scan_kernel<<<NBLK, SCAN_B>>>();
    finalize_start_kernel<<<NBLK, SCAN_B>>>(E);
    fill_kernel<<<(E + 255) / 256, 256>>>(edge_src, edge_dst, edge_val, E);

    int fw_grid = (N_NODES + FW_WARPS - 1) / FW_WARPS;
    fused_agg_gemm2_kernel<<<fw_grid, FW_WARPS * 32>>>(W2);

    spmm2_gather_kernel<<<fw_grid, FW_WARPS * 32>>>(out);
}